// round 16
// baseline (speedup 1.0000x reference)
#include <cuda_runtime.h>
#include <utility>

#define HH 256
#define WW 256
#define BB 16
#define CIN 32
#define COUT 32
#define KM 16

// Partial-S handoff: k1 writes per-h-half partial sums; k23 adds both.
__device__ float g_SreP[2][BB * CIN * KM], g_SimP[2][BB * CIN * KM];

// Packed f32x2 FMA: d = a*b + c elementwise on {lo,hi} fp32 pairs (FFMA2)
#define FMA2(d, a, b, c) \
    asm("fma.rn.f32x2 %0, %1, %2, %3;" : "=l"(d) : "l"(a), "l"(b), "l"(c))

__device__ __forceinline__ unsigned long long pack2(float lo, float hi) {
    unsigned long long d;
    asm("mov.b64 %0, {%1, %2};" : "=l"(d) : "f"(lo), "f"(hi));
    return d;
}
__device__ __forceinline__ void unpack2(unsigned long long v, float& lo, float& hi) {
    asm("mov.b64 {%0, %1}, %2;" : "=f"(lo), "=f"(hi) : "l"(v));
}

// ---------------------------------------------------------------------------
// Compile-time trig: cos/sin(pi*m/128), exact integer range reduction +
// deg-15/14 Taylor (err ~1e-11). Become FFMA 32-bit immediates.
// ---------------------------------------------------------------------------
constexpr __host__ __device__ double tp_sin(double x) {
    double x2 = x * x, t = x, s = x;
    t *= -x2 / 6.0;   s += t;
    t *= -x2 / 20.0;  s += t;
    t *= -x2 / 42.0;  s += t;
    t *= -x2 / 72.0;  s += t;
    t *= -x2 / 110.0; s += t;
    t *= -x2 / 156.0; s += t;
    t *= -x2 / 210.0; s += t;
    return s;
}
constexpr __host__ __device__ double tp_cos(double x) {
    double x2 = x * x, t = 1.0, s = 1.0;
    t *= -x2 / 2.0;   s += t;
    t *= -x2 / 12.0;  s += t;
    t *= -x2 / 30.0;  s += t;
    t *= -x2 / 56.0;  s += t;
    t *= -x2 / 90.0;  s += t;
    t *= -x2 / 132.0; s += t;
    t *= -x2 / 182.0; s += t;
    return s;
}
constexpr double C_PI = 3.14159265358979323846264338327950288;

constexpr __host__ __device__ float ccosm(int m) {   // cos(pi*m/128)
    m &= 255;
    double sgn = 1.0;
    if (m > 128) m = 256 - m;
    if (m > 64) { sgn = -1.0; m = 128 - m; }
    if (m == 64) return 0.0f;
    return (float)(sgn * tp_cos(C_PI * m / 128.0));
}
constexpr __host__ __device__ float csinm(int m) {   // sin(pi*m/128)
    m &= 255;
    double sgn = 1.0;
    if (m > 128) { sgn = -1.0; m = 256 - m; }
    if (m > 64) m = 128 - m;
    if (m == 0) return 0.0f;
    return (float)(sgn * tp_sin(C_PI * m / 128.0));
}
constexpr __host__ __device__ float cDr(int h) {   // Re D(h)
    double s = 0.0;
    for (int r = 0; r < KM; r++) s += (double)ccosm(r * h);
    return (float)s;
}
constexpr __host__ __device__ float cDi(int h) {   // Im D(h)
    double s = 0.0;
    for (int r = 0; r < KM; r++) s -= (double)csinm(r * h);
    return (float)s;
}

// ---------------------------------------------------------------------------
// K1 (h-split, R13 load structure): block = (bc, half); streams rows
// [half*128, half*128+128). Thread (q = t&63, stripe = t>>6) loads float4
// at column 4q, rows h = half*128 + stripe + 4j (j < 32), in 4 GROUPS of 8
// staged LDG.128 (MLP=8), FFMA-imm Dirichlet into per-component complex
// accumulators. Partial column-DFT (linear) written to g_S*P[half].
// ---------------------------------------------------------------------------
template <int H, int K>
__device__ __forceinline__ void k1_consume(const float4* v, float* acc) {
    constexpr float dr = cDr(H);
    constexpr float di = cDi(H);
    acc[0] = fmaf(v[K].x, dr, acc[0]);  acc[1] = fmaf(v[K].x, di, acc[1]);
    acc[2] = fmaf(v[K].y, dr, acc[2]);  acc[3] = fmaf(v[K].y, di, acc[3]);
    acc[4] = fmaf(v[K].z, dr, acc[4]);  acc[5] = fmaf(v[K].z, di, acc[5]);
    acc[6] = fmaf(v[K].w, dr, acc[6]);  acc[7] = fmaf(v[K].w, di, acc[7]);
}
template <int BASE, int G, int... Ks>
__device__ __forceinline__ void k1_group(const float4* __restrict__ xq, float* acc,
                                         std::integer_sequence<int, Ks...>) {
    float4 v[8];
    ((v[Ks] = xq[(BASE + 4 * (G * 8 + Ks)) * (WW / 4)]), ...);
    (k1_consume<BASE + 4 * (G * 8 + Ks), Ks>(v, acc), ...);
}
template <int BASE, int... Gs>
__device__ __forceinline__ void k1_groups(const float4* __restrict__ xq, float* acc,
                                          std::integer_sequence<int, Gs...>) {
    (k1_group<BASE, Gs>(xq, acc, std::make_integer_sequence<int, 8>{}), ...);
}

__global__ __launch_bounds__(256) void k1_S(const float* __restrict__ x) {
    int blk  = blockIdx.x;
    int bc   = blk >> 1;          // b*CIN + c
    int half = blk & 1;
    int t    = threadIdx.x;       // 0..255
    int q      = t & 63;          // float4 column
    int stripe = t >> 6;          // 0..3

    __shared__ float2 spart[4 * WW];      // [stripe][w] {yre,yim}
    __shared__ float  syre[WW], syim[WW];

    const float4* xq = reinterpret_cast<const float4*>(x + (size_t)bc * HH * WW) + q;
    float acc[8] = {0.f, 0.f, 0.f, 0.f, 0.f, 0.f, 0.f, 0.f};
    using GSeq = std::make_integer_sequence<int, 4>;   // 4 groups of 8 rows
    switch ((half << 2) | stripe) {
        case 0: k1_groups<0>(xq, acc, GSeq{});   break;
        case 1: k1_groups<1>(xq, acc, GSeq{});   break;
        case 2: k1_groups<2>(xq, acc, GSeq{});   break;
        case 3: k1_groups<3>(xq, acc, GSeq{});   break;
        case 4: k1_groups<128>(xq, acc, GSeq{}); break;
        case 5: k1_groups<129>(xq, acc, GSeq{}); break;
        case 6: k1_groups<130>(xq, acc, GSeq{}); break;
        default: k1_groups<131>(xq, acc, GSeq{}); break;
    }

    // PDL: this block's DRAM streaming is done — let k23's grid launch.
    cudaTriggerProgrammaticLaunchCompletion();

#pragma unroll
    for (int e = 0; e < 4; e++)
        spart[stripe * WW + 4 * q + e] = make_float2(acc[2 * e], acc[2 * e + 1]);
    __syncthreads();

    {
        int w = t;
        float2 a = spart[0 * WW + w], b2 = spart[1 * WW + w];
        float2 c = spart[2 * WW + w], d2 = spart[3 * WW + w];
        syre[w] = (a.x + b2.x) + (c.x + d2.x);
        syim[w] = (a.y + b2.y) + (c.y + d2.y);
    }
    __syncthreads();

    // 8 warps, each warp handles cols {warp, warp+8}; twiddles on the fly
    int warp = t >> 5, lane = t & 31;
    for (int cc = warp; cc < KM; cc += 8) {
        float are = 0.f, aim = 0.f;
#pragma unroll
        for (int it = 0; it < 8; it++) {
            int j = lane + it * 32;
            float s, c;
            sincospif((float)(cc * j) / 128.0f, &s, &c);
            float yr = syre[j], yi = syim[j];
            are = fmaf(yr, c, are);  are = fmaf(yi, s, are);
            aim = fmaf(yi, c, aim);  aim = fmaf(-yr, s, aim);
        }
#pragma unroll
        for (int off = 16; off; off >>= 1) {
            are += __shfl_down_sync(0xffffffffu, are, off);
            aim += __shfl_down_sync(0xffffffffu, aim, off);
        }
        if (lane == 0) {
            g_SreP[half][bc * KM + cc] = are * (1.0f / 256.0f);
            g_SimP[half][bc * KM + cc] = aim * (1.0f / 256.0f);
        }
    }
}

// ---------------------------------------------------------------------------
// K23 phase C body: fully unrolled, trig as FFMA immediates, 4-way h-fold,
// compile-time zero-term elision.
// ---------------------------------------------------------------------------
template <int H, int R>
__device__ __forceinline__ void k3_step(const float* pre, const float* pim,
                                        float& Ae, float& Ao, float& Be, float& Bo) {
    constexpr float cv = ccosm(R * H);
    constexpr float sv = csinm(R * H);
    if constexpr ((R & 1) != 0) {
        if constexpr (cv != 0.0f) Ao = fmaf(pre[R], cv, Ao);
        if constexpr (sv != 0.0f) Bo = fmaf(pim[R], sv, Bo);
    } else {
        if constexpr (cv != 0.0f) Ae = fmaf(pre[R], cv, Ae);
        if constexpr (sv != 0.0f) Be = fmaf(pim[R], sv, Be);
    }
}
template <int H, int... Rs>
__device__ __forceinline__ void k3_one(const float* pre, const float* pim,
                                       float* __restrict__ op,
                                       std::integer_sequence<int, Rs...>) {
    float Ae = 0.f, Ao = 0.f, Be = 0.f, Bo = 0.f;
    (k3_step<H, Rs>(pre, pim, Ae, Ao, Be, Bo), ...);
    float Apl = Ae + Ao, Ami = Ae - Ao;
    float Bpl = Be + Bo, Bmi = Be - Bo;
    op[(size_t)H * WW] = Apl - Bpl;
    if constexpr (H != 64)           op[(size_t)(128 - H) * WW] = Ami + Bmi;
    if constexpr (H >= 1)            op[(size_t)(256 - H) * WW] = Apl + Bpl;
    if constexpr (H >= 1 && H != 64) op[(size_t)(128 + H) * WW] = Ami - Bmi;
}
template <int... Hs>
__device__ __forceinline__ void k3_all(const float* pre, const float* pim,
                                       float* __restrict__ op,
                                       std::integer_sequence<int, Hs...>) {
    (k3_one<Hs>(pre, pim, op, std::make_integer_sequence<int, KM>{}), ...);
}

// ---------------------------------------------------------------------------
// K23 (fused, R15 body, frozen; only the S load now sums two partials):
// block = bo, 256 threads, 4 CTAs/SM. PDL prologue (twiddle seed + weight
// L2 prefetch) before cudaGridDependencySynchronize().
// ---------------------------------------------------------------------------
__global__ __launch_bounds__(256, 4) void k23(const float* __restrict__ wr,
                                              const float* __restrict__ wi,
                                              float* __restrict__ out) {
    int bo = blockIdx.x;       // b*COUT + o
    int b  = bo >> 5, o = bo & 31;
    int t  = threadIdx.x;      // 0..255

    __shared__ float  sSre[CIN * KM], sSim[CIN * KM];  // [i][r]
    __shared__ float4 sBq[KM * KM];                    // [r][c] {bre,bre,-bim,bim}

    // ---- PDL prologue: independent of k1 ----
    int w = t;
    float s1, c1;
    sincospif((float)w / 128.0f, &s1, &c1);   // e^{+i*pi*w/128}

    {
        int r = t >> 4, c = t & 15;
        if (c == 0) {
#pragma unroll
            for (int i = 0; i < CIN; i++) {
                size_t widx = (((size_t)i * COUT + o) * KM + r) * KM;
                asm volatile("prefetch.global.L2 [%0];" :: "l"(wr + widx));
                asm volatile("prefetch.global.L2 [%0];" :: "l"(wi + widx));
            }
        }
    }

    // ---- Wait for k1's grid (memory visibility for g_S partials) ----
    cudaGridDependencySynchronize();

    for (int idx = t; idx < CIN * KM; idx += 256) {
        int off = b * CIN * KM + idx;
        sSre[idx] = g_SreP[0][off] + g_SreP[1][off];
        sSim[idx] = g_SimP[0][off] + g_SimP[1][off];
    }
    __syncthreads();

    // Phase A: blk, thread = r*16 + c (full unroll; 32-deep load MLP)
    {
        int r = t >> 4, c = t & 15;
        float bre = 0.f, bim = 0.f;
#pragma unroll
        for (int i = 0; i < CIN; i++) {
            float sre = sSre[i * KM + r], sim = sSim[i * KM + r];
            size_t widx = (((size_t)i * COUT + o) * KM + r) * KM + c;
            float wre = wr[widx], wim = wi[widx];
            bre = fmaf(sre, wre, bre);  bre = fmaf(-sim, wim, bre);
            bim = fmaf(sre, wim, bim);  bim = fmaf(sim, wre, bim);
        }
        float a = (c == 0 ? 1.0f : 2.0f) * (1.0f / 256.0f);
        bre *= a;
        bim *= a;
        sBq[t] = make_float4(bre, bre, -bim, bim);
    }
    __syncthreads();

    // Phase B: packed pp[r] = {ReP, ImP}; c=0 direct, c>=1 twiddle recurrence
    unsigned long long pp[KM];
#pragma unroll
    for (int r = 0; r < KM; r++) {
        float4 q = sBq[r * KM + 0];
        pp[r] = pack2(q.x, q.w);    // {bre, bim}
    }

    float tc = c1, ts = s1;         // twiddle for c = 1
#pragma unroll
    for (int c = 1; c < KM; c++) {
        unsigned long long P1 = pack2(tc, ts);   // {tc, ts}
        unsigned long long P2 = pack2(ts, tc);   // {ts, tc}
#pragma unroll
        for (int r = 0; r < KM; r++) {
            ulonglong2 bv = *reinterpret_cast<const ulonglong2*>(&sBq[r * KM + c]);
            FMA2(pp[r], bv.x, P1, pp[r]);
            FMA2(pp[r], bv.y, P2, pp[r]);
        }
        float ntc = fmaf(tc, c1, -ts * s1);
        float nts = fmaf(tc, s1,  ts * c1);
        tc = ntc;
        ts = nts;
    }

    float pre[KM], pim[KM];
#pragma unroll
    for (int r = 0; r < KM; r++) unpack2(pp[r], pre[r], pim[r]);

    float* op = out + (size_t)bo * HH * WW + w;
    k3_all(pre, pim, op, std::make_integer_sequence<int, 65>{});
}

// ---------------------------------------------------------------------------
// Launch: k1 (grid 1024, h-split) normally; k23 with programmatic stream
// serialization (PDL) so its CTAs launch under k1's tail.
// ---------------------------------------------------------------------------
extern "C" void kernel_launch(void* const* d_in, const int* in_sizes, int n_in,
                              void* d_out, int out_size) {
    const float* x  = (const float*)d_in[0];
    const float* wr = (const float*)d_in[1];
    const float* wi = (const float*)d_in[2];
    float* out = (float*)d_out;

    k1_S<<<BB * CIN * 2, 256>>>(x);

    cudaLaunchConfig_t cfg = {};
    cfg.gridDim  = dim3(BB * COUT, 1, 1);
    cfg.blockDim = dim3(256, 1, 1);
    cfg.dynamicSmemBytes = 0;
    cfg.stream = 0;
    cudaLaunchAttribute attr[1];
    attr[0].id = cudaLaunchAttributeProgrammaticStreamSerialization;
    attr[0].val.programmaticStreamSerializationAllowed = 1;
    cfg.attrs = attr;
    cfg.numAttrs = 1;
    cudaLaunchKernelEx(&cfg, k23, wr, wi, out);
}

// round 17
// speedup vs baseline: 1.1145x; 1.1145x over previous
#include <cuda_runtime.h>
#include <utility>

#define HH 256
#define WW 256
#define BB 16
#define CIN 32
#define COUT 32
#define KM 16

// S handoff between k1 and k23 (allocation-free scratch)
__device__ float g_Sre[BB * CIN * KM], g_Sim[BB * CIN * KM];

// Packed f32x2 FMA: d = a*b + c elementwise on {lo,hi} fp32 pairs (FFMA2)
#define FMA2(d, a, b, c) \
    asm("fma.rn.f32x2 %0, %1, %2, %3;" : "=l"(d) : "l"(a), "l"(b), "l"(c))

__device__ __forceinline__ unsigned long long pack2(float lo, float hi) {
    unsigned long long d;
    asm("mov.b64 %0, {%1, %2};" : "=l"(d) : "f"(lo), "f"(hi));
    return d;
}
__device__ __forceinline__ void unpack2(unsigned long long v, float& lo, float& hi) {
    asm("mov.b64 {%0, %1}, %2;" : "=f"(lo), "=f"(hi) : "l"(v));
}

// ---------------------------------------------------------------------------
// Compile-time trig: cos/sin(pi*m/128), exact integer range reduction +
// deg-15/14 Taylor (err ~1e-11). Become FFMA 32-bit immediates.
// ---------------------------------------------------------------------------
constexpr __host__ __device__ double tp_sin(double x) {
    double x2 = x * x, t = x, s = x;
    t *= -x2 / 6.0;   s += t;
    t *= -x2 / 20.0;  s += t;
    t *= -x2 / 42.0;  s += t;
    t *= -x2 / 72.0;  s += t;
    t *= -x2 / 110.0; s += t;
    t *= -x2 / 156.0; s += t;
    t *= -x2 / 210.0; s += t;
    return s;
}
constexpr __host__ __device__ double tp_cos(double x) {
    double x2 = x * x, t = 1.0, s = 1.0;
    t *= -x2 / 2.0;   s += t;
    t *= -x2 / 12.0;  s += t;
    t *= -x2 / 30.0;  s += t;
    t *= -x2 / 56.0;  s += t;
    t *= -x2 / 90.0;  s += t;
    t *= -x2 / 132.0; s += t;
    t *= -x2 / 182.0; s += t;
    return s;
}
constexpr double C_PI = 3.14159265358979323846264338327950288;

constexpr __host__ __device__ float ccosm(int m) {   // cos(pi*m/128)
    m &= 255;
    double sgn = 1.0;
    if (m > 128) m = 256 - m;
    if (m > 64) { sgn = -1.0; m = 128 - m; }
    if (m == 64) return 0.0f;
    return (float)(sgn * tp_cos(C_PI * m / 128.0));
}
constexpr __host__ __device__ float csinm(int m) {   // sin(pi*m/128)
    m &= 255;
    double sgn = 1.0;
    if (m > 128) { sgn = -1.0; m = 256 - m; }
    if (m > 64) m = 128 - m;
    if (m == 0) return 0.0f;
    return (float)(sgn * tp_sin(C_PI * m / 128.0));
}
constexpr __host__ __device__ float cDr(int h) {   // Re D(h)
    double s = 0.0;
    for (int r = 0; r < KM; r++) s += (double)ccosm(r * h);
    return (float)s;
}
constexpr __host__ __device__ float cDi(int h) {   // Im D(h)
    double s = 0.0;
    for (int r = 0; r < KM; r++) s -= (double)csinm(r * h);
    return (float)s;
}

// ---------------------------------------------------------------------------
// K1 (R15 winner, frozen shape): block = bc (512 blocks, full 256 rows).
// Thread (q = t&63, stripe = t>>6) loads float4 at column 4q, rows
// h = stripe + 4j (j < 64), in 8 GROUPS of 8 staged LDG.128 (MLP=8) with
// evict-first (.cs) policy — x is streamed once, keep L2 for weights/S.
// FFMA-imm Dirichlet into per-component complex accumulators.
// ---------------------------------------------------------------------------
template <int H, int K>
__device__ __forceinline__ void k1_consume(const float4* v, float* acc) {
    constexpr float dr = cDr(H);
    constexpr float di = cDi(H);
    acc[0] = fmaf(v[K].x, dr, acc[0]);  acc[1] = fmaf(v[K].x, di, acc[1]);
    acc[2] = fmaf(v[K].y, dr, acc[2]);  acc[3] = fmaf(v[K].y, di, acc[3]);
    acc[4] = fmaf(v[K].z, dr, acc[4]);  acc[5] = fmaf(v[K].z, di, acc[5]);
    acc[6] = fmaf(v[K].w, dr, acc[6]);  acc[7] = fmaf(v[K].w, di, acc[7]);
}
template <int STRIPE, int G, int... Ks>
__device__ __forceinline__ void k1_group(const float4* __restrict__ xq, float* acc,
                                         std::integer_sequence<int, Ks...>) {
    float4 v[8];
    ((v[Ks] = __ldcs(&xq[(STRIPE + 4 * (G * 8 + Ks)) * (WW / 4)])), ...);
    (k1_consume<STRIPE + 4 * (G * 8 + Ks), Ks>(v, acc), ...);
}
template <int STRIPE, int... Gs>
__device__ __forceinline__ void k1_groups(const float4* __restrict__ xq, float* acc,
                                          std::integer_sequence<int, Gs...>) {
    (k1_group<STRIPE, Gs>(xq, acc, std::make_integer_sequence<int, 8>{}), ...);
}

__global__ __launch_bounds__(256) void k1_S(const float* __restrict__ x) {
    int bc = blockIdx.x;          // b*CIN + c
    int t  = threadIdx.x;         // 0..255
    int q      = t & 63;          // float4 column
    int stripe = t >> 6;          // 0..3

    __shared__ float2 spart[4 * WW];      // [stripe][w] {yre,yim}
    __shared__ float  syre[WW], syim[WW];

    const float4* xq = reinterpret_cast<const float4*>(x + (size_t)bc * HH * WW) + q;
    float acc[8] = {0.f, 0.f, 0.f, 0.f, 0.f, 0.f, 0.f, 0.f};
    using GSeq = std::make_integer_sequence<int, 8>;
    switch (stripe) {
        case 0: k1_groups<0>(xq, acc, GSeq{}); break;
        case 1: k1_groups<1>(xq, acc, GSeq{}); break;
        case 2: k1_groups<2>(xq, acc, GSeq{}); break;
        default: k1_groups<3>(xq, acc, GSeq{}); break;
    }

    // PDL: streaming (the DRAM-bound 90%) is done — let k23's grid launch.
    cudaTriggerProgrammaticLaunchCompletion();

#pragma unroll
    for (int e = 0; e < 4; e++)
        spart[stripe * WW + 4 * q + e] = make_float2(acc[2 * e], acc[2 * e + 1]);
    __syncthreads();

    {
        int w = t;
        float2 a = spart[0 * WW + w], b2 = spart[1 * WW + w];
        float2 c = spart[2 * WW + w], d2 = spart[3 * WW + w];
        syre[w] = (a.x + b2.x) + (c.x + d2.x);
        syim[w] = (a.y + b2.y) + (c.y + d2.y);
    }
    __syncthreads();

    // 8 warps, each warp handles cols {warp, warp+8}; twiddles on the fly
    int warp = t >> 5, lane = t & 31;
    for (int cc = warp; cc < KM; cc += 8) {
        float are = 0.f, aim = 0.f;
#pragma unroll
        for (int it = 0; it < 8; it++) {
            int j = lane + it * 32;
            float s, c;
            sincospif((float)(cc * j) / 128.0f, &s, &c);
            float yr = syre[j], yi = syim[j];
            are = fmaf(yr, c, are);  are = fmaf(yi, s, are);
            aim = fmaf(yi, c, aim);  aim = fmaf(-yr, s, aim);
        }
#pragma unroll
        for (int off = 16; off; off >>= 1) {
            are += __shfl_down_sync(0xffffffffu, are, off);
            aim += __shfl_down_sync(0xffffffffu, aim, off);
        }
        if (lane == 0) {
            g_Sre[bc * KM + cc] = are * (1.0f / 256.0f);
            g_Sim[bc * KM + cc] = aim * (1.0f / 256.0f);
        }
    }
}

// ---------------------------------------------------------------------------
// K23 phase C body: fully unrolled, trig as FFMA immediates, 4-way h-fold,
// compile-time zero-term elision. Output via evict-first (.cs) stores —
// write-once data, keep L2 for the weight working set.
// ---------------------------------------------------------------------------
template <int H, int R>
__device__ __forceinline__ void k3_step(const float* pre, const float* pim,
                                        float& Ae, float& Ao, float& Be, float& Bo) {
    constexpr float cv = ccosm(R * H);
    constexpr float sv = csinm(R * H);
    if constexpr ((R & 1) != 0) {
        if constexpr (cv != 0.0f) Ao = fmaf(pre[R], cv, Ao);
        if constexpr (sv != 0.0f) Bo = fmaf(pim[R], sv, Bo);
    } else {
        if constexpr (cv != 0.0f) Ae = fmaf(pre[R], cv, Ae);
        if constexpr (sv != 0.0f) Be = fmaf(pim[R], sv, Be);
    }
}
template <int H, int... Rs>
__device__ __forceinline__ void k3_one(const float* pre, const float* pim,
                                       float* __restrict__ op,
                                       std::integer_sequence<int, Rs...>) {
    float Ae = 0.f, Ao = 0.f, Be = 0.f, Bo = 0.f;
    (k3_step<H, Rs>(pre, pim, Ae, Ao, Be, Bo), ...);
    float Apl = Ae + Ao, Ami = Ae - Ao;
    float Bpl = Be + Bo, Bmi = Be - Bo;
    __stcs(&op[(size_t)H * WW], Apl - Bpl);
    if constexpr (H != 64)           __stcs(&op[(size_t)(128 - H) * WW], Ami + Bmi);
    if constexpr (H >= 1)            __stcs(&op[(size_t)(256 - H) * WW], Apl + Bpl);
    if constexpr (H >= 1 && H != 64) __stcs(&op[(size_t)(128 + H) * WW], Ami - Bmi);
}
template <int... Hs>
__device__ __forceinline__ void k3_all(const float* pre, const float* pim,
                                       float* __restrict__ op,
                                       std::integer_sequence<int, Hs...>) {
    (k3_one<Hs>(pre, pim, op, std::make_integer_sequence<int, KM>{}), ...);
}

// ---------------------------------------------------------------------------
// K23 (fused, R15 body, frozen): block = bo, 256 threads, 4 CTAs/SM.
//   PDL prologue (twiddle seed + weight L2 prefetch) before
//   cudaGridDependencySynchronize(); then phase A (full i-unroll), phase B
//   (c=0 direct + twiddle recurrence), phase C (immediate-trig, 4-way fold).
// ---------------------------------------------------------------------------
__global__ __launch_bounds__(256, 4) void k23(const float* __restrict__ wr,
                                              const float* __restrict__ wi,
                                              float* __restrict__ out) {
    int bo = blockIdx.x;       // b*COUT + o
    int b  = bo >> 5, o = bo & 31;
    int t  = threadIdx.x;      // 0..255

    __shared__ float  sSre[CIN * KM], sSim[CIN * KM];  // [i][r]
    __shared__ float4 sBq[KM * KM];                    // [r][c] {bre,bre,-bim,bim}

    // ---- PDL prologue: independent of k1 ----
    int w = t;
    float s1, c1;
    sincospif((float)w / 128.0f, &s1, &c1);   // e^{+i*pi*w/128}

    {
        int r = t >> 4, c = t & 15;
        if (c == 0) {
#pragma unroll
            for (int i = 0; i < CIN; i++) {
                size_t widx = (((size_t)i * COUT + o) * KM + r) * KM;
                asm volatile("prefetch.global.L2 [%0];" :: "l"(wr + widx));
                asm volatile("prefetch.global.L2 [%0];" :: "l"(wi + widx));
            }
        }
    }

    // ---- Wait for k1's grid (memory visibility for g_S) ----
    cudaGridDependencySynchronize();

    for (int idx = t; idx < CIN * KM; idx += 256) {
        sSre[idx] = g_Sre[b * CIN * KM + idx];
        sSim[idx] = g_Sim[b * CIN * KM + idx];
    }
    __syncthreads();

    // Phase A: blk, thread = r*16 + c (full unroll; 32-deep load MLP)
    {
        int r = t >> 4, c = t & 15;
        float bre = 0.f, bim = 0.f;
#pragma unroll
        for (int i = 0; i < CIN; i++) {
            float sre = sSre[i * KM + r], sim = sSim[i * KM + r];
            size_t widx = (((size_t)i * COUT + o) * KM + r) * KM + c;
            float wre = wr[widx], wim = wi[widx];
            bre = fmaf(sre, wre, bre);  bre = fmaf(-sim, wim, bre);
            bim = fmaf(sre, wim, bim);  bim = fmaf(sim, wre, bim);
        }
        float a = (c == 0 ? 1.0f : 2.0f) * (1.0f / 256.0f);
        bre *= a;
        bim *= a;
        sBq[t] = make_float4(bre, bre, -bim, bim);
    }
    __syncthreads();

    // Phase B: packed pp[r] = {ReP, ImP}; c=0 direct, c>=1 twiddle recurrence
    unsigned long long pp[KM];
#pragma unroll
    for (int r = 0; r < KM; r++) {
        float4 q = sBq[r * KM + 0];
        pp[r] = pack2(q.x, q.w);    // {bre, bim}
    }

    float tc = c1, ts = s1;         // twiddle for c = 1
#pragma unroll
    for (int c = 1; c < KM; c++) {
        unsigned long long P1 = pack2(tc, ts);   // {tc, ts}
        unsigned long long P2 = pack2(ts, tc);   // {ts, tc}
#pragma unroll
        for (int r = 0; r < KM; r++) {
            ulonglong2 bv = *reinterpret_cast<const ulonglong2*>(&sBq[r * KM + c]);
            FMA2(pp[r], bv.x, P1, pp[r]);
            FMA2(pp[r], bv.y, P2, pp[r]);
        }
        float ntc = fmaf(tc, c1, -ts * s1);
        float nts = fmaf(tc, s1,  ts * c1);
        tc = ntc;
        ts = nts;
    }

    float pre[KM], pim[KM];
#pragma unroll
    for (int r = 0; r < KM; r++) unpack2(pp[r], pre[r], pim[r]);

    float* op = out + (size_t)bo * HH * WW + w;
    k3_all(pre, pim, op, std::make_integer_sequence<int, 65>{});
}

// ---------------------------------------------------------------------------
// Launch: k1 (512 blocks) normally; k23 with programmatic stream
// serialization (PDL) so its CTAs launch under k1's tail.
// ---------------------------------------------------------------------------
extern "C" void kernel_launch(void* const* d_in, const int* in_sizes, int n_in,
                              void* d_out, int out_size) {
    const float* x  = (const float*)d_in[0];
    const float* wr = (const float*)d_in[1];
    const float* wi = (const float*)d_in[2];
    float* out = (float*)d_out;

    k1_S<<<BB * CIN, 256>>>(x);

    cudaLaunchConfig_t cfg = {};
    cfg.gridDim  = dim3(BB * COUT, 1, 1);
    cfg.blockDim = dim3(256, 1, 1);
    cfg.dynamicSmemBytes = 0;
    cfg.stream = 0;
    cudaLaunchAttribute attr[1];
    attr[0].id = cudaLaunchAttributeProgrammaticStreamSerialization;
    attr[0].val.programmaticStreamSerializationAllowed = 1;
    cfg.attrs = attr;
    cfg.numAttrs = 1;
    cudaLaunchKernelEx(&cfg, k23, wr, wi, out);
}